// round 8
// baseline (speedup 1.0000x reference)
#include <cuda_runtime.h>
#include <math_constants.h>

#define BATCH 2
#define NPTS 1024
#define KNN 8
#define TI 2
#define THREADS 256
#define NW (THREADS / 32)

// FACTOR_A = 180 / (15 * pi) = 12/pi
#define FACTOR_A 3.8197186342054885f

typedef unsigned long long u64;

// Single-MUFU approximate sqrt (sqrt.approx.f32: ~2^-23 rel err, +0 -> +0).
__device__ __forceinline__ float fsqrt_fast(float x) {
    float r;
    asm("sqrt.approx.f32 %0, %1;" : "=f"(r) : "f"(x));
    return r;
}

// ---- packed f32x2 helpers (Blackwell; ptxas never auto-emits these) ----
__device__ __forceinline__ u64 pack2(float lo, float hi) {
    u64 r; asm("mov.b64 %0, {%1, %2};" : "=l"(r) : "f"(lo), "f"(hi)); return r;
}
__device__ __forceinline__ float2 unpack2(u64 v) {
    float lo, hi;
    asm("mov.b64 {%0, %1}, %2;" : "=f"(lo), "=f"(hi) : "l"(v));
    return make_float2(lo, hi);
}
__device__ __forceinline__ u64 ffma2(u64 a, u64 b, u64 c) {
    u64 r; asm("fma.rn.f32x2 %0, %1, %2, %3;" : "=l"(r) : "l"(a), "l"(b), "l"(c));
    return r;
}
__device__ __forceinline__ u64 fmul2(u64 a, u64 b) {
    u64 r; asm("mul.rn.f32x2 %0, %1, %2;" : "=l"(r) : "l"(a), "l"(b)); return r;
}
__device__ __forceinline__ u64 fadd2(u64 a, u64 b) {
    u64 r; asm("add.rn.f32x2 %0, %1, %2;" : "=l"(r) : "l"(a), "l"(b)); return r;
}

// Branchless acos, Abramowitz-Stegun 4.4.45 (|err| <= 6.7e-5 rad). Clamps internally.
__device__ __forceinline__ float facos(float x) {
    float ax = fminf(fabsf(x), 1.0f);
    float p = fmaf(ax, -0.0187293f, 0.0742610f);
    p = fmaf(ax, p, -0.2121144f);
    p = fmaf(ax, p, 1.5707288f);
    float s = fsqrt_fast(1.0f - ax) * p;
    return (x >= 0.0f) ? s : (CUDART_PI_F - s);
}

__global__ __launch_bounds__(THREADS)
void gse_kernel(const float* __restrict__ points,
                const float* __restrict__ normals,
                float* __restrict__ cat_out,   // [B,N,N,3]
                float* __restrict__ a_out)     // [B,N,N,K]
{
    __shared__ float4   P[NPTS];          // x, y, z, |p|^2 (strict rounding)
    __shared__ float4   Nn[NPTS];         // nx, ny, nz, 1/|n|
    __shared__ unsigned wval[NW * KNN];   // per-warp top-8 candidate dist-bits
    __shared__ unsigned widx[NW * KNN];
    __shared__ float    rkv[KNN][3];      // normalized ref vectors

    const int b    = blockIdx.x >> 9;            // N/TI = 512 blocks per batch
    const int i0   = (blockIdx.x & 511) * TI;
    const int tid  = threadIdx.x;
    const int lane = tid & 31;
    const int wid  = tid >> 5;

    // packed poly constants for FACTOR_A * acos (pi * FACTOR_A == 12 exactly)
    const u64 K0_2  = pack2(-0.0187293f * FACTOR_A, -0.0187293f * FACTOR_A);
    const u64 K1_2  = pack2( 0.0742610f * FACTOR_A,  0.0742610f * FACTOR_A);
    const u64 K2_2  = pack2(-0.2121144f * FACTOR_A, -0.2121144f * FACTOR_A);
    const u64 K3_2  = pack2( 1.5707288f * FACTOR_A,  1.5707288f * FACTOR_A);
    const u64 ONE_2 = pack2(1.0f, 1.0f);

    // ---- load batch points/normals into smem ----
    const float* pb = points  + (size_t)b * NPTS * 3;
    const float* nb = normals + (size_t)b * NPTS * 3;
    for (int j = tid; j < NPTS; j += THREADS) {
        float x = pb[3 * j], y = pb[3 * j + 1], z = pb[3 * j + 2];
        // strict emulation of jnp.sum(p*p,-1): ((x*x)+(y*y))+(z*z), each rounded
        float sqs = __fadd_rn(__fadd_rn(__fmul_rn(x, x), __fmul_rn(y, y)),
                              __fmul_rn(z, z));
        P[j] = make_float4(x, y, z, sqs);
        float nx = nb[3 * j], ny = nb[3 * j + 1], nz = nb[3 * j + 2];
        float nn = sqrtf(nx * nx + ny * ny + nz * nz);
        Nn[j] = make_float4(nx, ny, nz, __fdividef(1.0f, nn));
    }
    __syncthreads();

    for (int ii = 0; ii < TI; ii++) {
        const int i = i0 + ii;
        const float4 Pi = P[i];
        const float pix = Pi.x, piy = Pi.y, piz = Pi.z, sqis = Pi.w;

        // ---- phase A: strict fp32 selection distances (bit-exact vs jax) ----
        float v[4]; int ix[4];
        #pragma unroll
        for (int s = 0; s < 4; s++) {
            int j = tid + s * THREADS;
            float4 Pj = P[j];
            float dot = __fadd_rn(__fadd_rn(__fmul_rn(pix, Pj.x),
                                            __fmul_rn(piy, Pj.y)),
                                  __fmul_rn(piz, Pj.z));
            float d2 = __fsub_rn(__fadd_rn(sqis, Pj.w), __fmul_rn(2.0f, dot));
            float dist = __fsqrt_rn(fmaxf(d2, 0.0f));
            v[s]  = (j == i) ? CUDART_INF_F : dist;  // drop self (== idx[...,0])
            ix[s] = j;
        }

        // ---- phase B1: sort-4 then redux-based top-8 extraction ----
        #define CSWAP(a, bb)                                                  \
            {                                                                 \
                bool sw = (v[bb] < v[a]) ||                                   \
                          (v[bb] == v[a] && ix[bb] < ix[a]);                  \
                float tv = sw ? v[bb] : v[a];                                 \
                v[bb] = sw ? v[a] : v[bb];  v[a] = tv;                        \
                int ti = sw ? ix[bb] : ix[a];                                 \
                ix[bb] = sw ? ix[a] : ix[bb]; ix[a] = ti;                     \
            }
        CSWAP(0, 1) CSWAP(2, 3) CSWAP(0, 2) CSWAP(1, 3) CSWAP(1, 2)
        #undef CSWAP

        #pragma unroll
        for (int k = 0; k < KNN; k++) {
            unsigned fb   = __float_as_uint(v[0]);     // nonneg -> bits monotonic
            unsigned minb = __reduce_min_sync(0xffffffffu, fb);
            unsigned cand = (fb == minb) ? (unsigned)ix[0] : 0xffffffffu;
            unsigned wmin = __reduce_min_sync(0xffffffffu, cand);
            if (fb == minb && (unsigned)ix[0] == wmin) {   // unique winner pops
                v[0] = v[1]; ix[0] = ix[1];
                v[1] = v[2]; ix[1] = ix[2];
                v[2] = v[3]; ix[2] = ix[3];
                v[3] = CUDART_INF_F;
            }
            if (lane == 0) { wval[wid * KNN + k] = minb; widx[wid * KNN + k] = wmin; }
        }
        __syncthreads();

        // ---- phase B2: warp 0 merges 64 candidates; winners build rkv inline ----
        if (wid == 0) {
            unsigned mv0 = wval[lane],  mv1 = wval[lane + 32];
            unsigned id0 = widx[lane],  id1 = widx[lane + 32];
            int myj = 0;
            #pragma unroll
            for (int k = 0; k < KNN; k++) {
                bool sel1 = (mv1 < mv0) || (mv1 == mv0 && id1 < id0);
                unsigned fv = sel1 ? mv1 : mv0;
                unsigned fi = sel1 ? id1 : id0;
                unsigned minb = __reduce_min_sync(0xffffffffu, fv);
                unsigned cand = (fv == minb) ? fi : 0xffffffffu;
                unsigned wmin = __reduce_min_sync(0xffffffffu, cand);
                if (fv == minb && fi == wmin) {
                    if (sel1) mv1 = 0xffffffffu; else mv0 = 0xffffffffu;
                }
                if (lane == k) myj = (int)wmin;   // wmin is warp-uniform
            }
            if (lane < KNN) {
                float rx = P[myj].x - pix, ry = P[myj].y - piy, rz = P[myj].z - piz;
                float rinv = __fdividef(1.0f, sqrtf(rx * rx + ry * ry + rz * rz));
                rkv[lane][0] = rx * rinv;
                rkv[lane][1] = ry * rinv;
                rkv[lane][2] = rz * rinv;
            }
        }
        __syncthreads();

        // normalized ref vectors, packed in f32x2 pairs (k, k+1)
        u64 rkx2[4], rky2[4], rkz2[4];
        #pragma unroll
        for (int p = 0; p < 4; p++) {
            rkx2[p] = pack2(rkv[2 * p][0], rkv[2 * p + 1][0]);
            rky2[p] = pack2(rkv[2 * p][1], rkv[2 * p + 1][1]);
            rkz2[p] = pack2(rkv[2 * p][2], rkv[2 * p + 1][2]);
        }

        const float4 Ni = Nn[i];
        const float nix = Ni.x, niy = Ni.y, niz = Ni.z, rnni = Ni.w;
        float* catRow = cat_out + ((size_t)(b * NPTS + i)) * NPTS * 3;
        float* aRow   = a_out   + ((size_t)(b * NPTS + i)) * NPTS * KNN;

        // ---- phase C: full pair row ----
        for (int j = tid; j < NPTS; j += THREADS) {
            float4 Pj = P[j];
            float4 Nj = Nn[j];
            float dx = Pj.x - pix, dy = Pj.y - piy, dz = Pj.z - piz;
            float dd = fmaf(dx, dx, fmaf(dy, dy, dz * dz));
            float l  = fsqrt_fast(dd);              // +0 on diagonal
            float linv = __fdividef(1.0f, l);       // inf on diagonal

            float dist = l * 5.0f;                  // dist_map / SIGMA_D

            // rad[i,j], rad[j,i]: EPS dropped (rel perturbation ~3e-7);
            // diagonal -> ci=cj=NaN -> facos=pi both -> angle=0 (matches ref).
            float doti = fmaf(nix, dx, fmaf(niy, dy, niz * dz));
            float radij = facos(doti * rnni * linv);

            float dotj = -fmaf(Nj.x, dx, fmaf(Nj.y, dy, Nj.z * dz));
            float radji = facos(dotj * Nj.w * linv);

            float angle = fabsf(radij - radji);

            // seta
            float nnd = fmaf(nix, Nj.x, fmaf(niy, Nj.y, niz * Nj.z));
            float seta = facos(nnd * rnni * Nj.w);

            catRow[j * 3 + 0] = dist;
            catRow[j * 3 + 1] = seta;
            catRow[j * 3 + 2] = angle;

            // a_indices: FACTOR_A*acos(r_hat . d_hat), packed 2 k's per f32x2 op
            float ux = dx * linv, uy = dy * linv, uz = dz * linv;
            u64 ux2 = pack2(ux, ux), uy2 = pack2(uy, uy), uz2 = pack2(uz, uz);
            float av[KNN];
            #pragma unroll
            for (int p = 0; p < 4; p++) {
                u64 cc = ffma2(rkx2[p], ux2,
                         ffma2(rky2[p], uy2, fmul2(rkz2[p], uz2)));
                u64 ax = cc & 0x7FFFFFFF7FFFFFFFULL;            // |c|
                u64 pol = ffma2(ax, K0_2, K1_2);
                pol = ffma2(ax, pol, K2_2);
                pol = ffma2(ax, pol, K3_2);
                u64 om = fadd2(ONE_2, ax ^ 0x8000000080000000ULL);  // 1 - |c|
                float2 o = unpack2(om);
                float2 pq = unpack2(pol);
                float2 c2 = unpack2(cc);
                float s0 = fsqrt_fast(fmaxf(o.x, 0.0f)) * pq.x;
                float s1 = fsqrt_fast(fmaxf(o.y, 0.0f)) * pq.y;
                av[2 * p]     = (c2.x >= 0.0f) ? s0 : (12.0f - s0);
                av[2 * p + 1] = (c2.y >= 0.0f) ? s1 : (12.0f - s1);
            }
            // diagonal: reference yields exactly 0 (XLA +0-init sum; arctan2(+0,+0)=0)
            if (j == i) {
                #pragma unroll
                for (int k = 0; k < KNN; k++) av[k] = 0.0f;
            }
            float4* ap = reinterpret_cast<float4*>(aRow + (size_t)j * KNN);
            ap[0] = make_float4(av[0], av[1], av[2], av[3]);
            ap[1] = make_float4(av[4], av[5], av[6], av[7]);
        }
        // no trailing barrier: next row's post-B1/post-B2 barriers already order
        // wval/rkv reuse (writes happen after every warp's reads, proven by bar order)
    }
}

extern "C" void kernel_launch(void* const* d_in, const int* in_sizes, int n_in,
                              void* d_out, int out_size)
{
    const float* points  = (const float*)d_in[0];
    const float* normals = (const float*)d_in[1];
    (void)in_sizes; (void)n_in; (void)out_size;

    float* out  = (float*)d_out;
    float* cat  = out;                                   // [B,N,N,3]
    float* aidx = out + (size_t)BATCH * NPTS * NPTS * 3; // [B,N,N,K]

    gse_kernel<<<BATCH * (NPTS / TI), THREADS>>>(points, normals, cat, aidx);
}